// round 6
// baseline (speedup 1.0000x reference)
#include <cuda_runtime.h>
#include <math.h>

#define MAIN_BLOCKS 1184
#define MAIN_TPB    256

__device__ float g_part_nll[MAIN_BLOCKS];
__device__ float g_part_w1[MAIN_BLOCKS];
__device__ float g_part_w2[MAIN_BLOCKS];
__device__ unsigned int g_count = 0;   // wraps back to 0 every launch (atomicInc modulus)

// picked = label ? p : 1-p, clamped at 1e-8 (reference's eliminate_0), then log.
static __device__ __forceinline__ float pick_log(float p, unsigned int l) {
    float pick = l ? p : (1.0f - p);
    pick = fmaxf(pick, 1e-8f);
    return __logf(pick);
}

static __device__ __forceinline__ float warp_red(float v) {
    #pragma unroll
    for (int o = 16; o; o >>= 1) v += __shfl_down_sync(0xFFFFFFFFu, v, o);
    return v;
}

static __device__ __forceinline__ double warp_red_d(double v) {
    #pragma unroll
    for (int o = 16; o; o >>= 1) v += __shfl_down_sync(0xFFFFFFFFu, v, o);
    return v;
}

extern "C" __global__ void __launch_bounds__(MAIN_TPB, 8)
fused_kernel(const float4* __restrict__ p4,
             const uint4*  __restrict__ l4,   // labels as int32: 4 per uint4
             const float4* __restrict__ w1,
             const float4* __restrict__ w2,
             float* __restrict__ out,
             int nq, int nw1, int nw2, double invN) {
    const int stride = gridDim.x * blockDim.x;
    const int t0 = blockIdx.x * blockDim.x + threadIdx.x;

    float accL = 0.0f;
    // NLL part: one float4 of probs + one uint4 of int32 labels per step.
    for (int i = t0; i < nq; i += stride) {
        float4 p = __ldcs(p4 + i);
        uint4  l = __ldcs(l4 + i);
        accL += pick_log(p.x, l.x);
        accL += pick_log(p.y, l.y);
        accL += pick_log(p.z, l.z);
        accL += pick_log(p.w, l.w);
    }

    float a1 = 0.0f;
    for (int i = t0; i < nw1; i += stride) {
        float4 v = __ldcs(w1 + i);
        a1 = fmaf(v.x, v.x, a1); a1 = fmaf(v.y, v.y, a1);
        a1 = fmaf(v.z, v.z, a1); a1 = fmaf(v.w, v.w, a1);
    }

    float a2 = 0.0f;
    for (int i = t0; i < nw2; i += stride) {
        float4 v = __ldcs(w2 + i);
        a2 = fmaf(v.x, v.x, a2); a2 = fmaf(v.y, v.y, a2);
        a2 = fmaf(v.z, v.z, a2); a2 = fmaf(v.w, v.w, a2);
    }

    // Block reduction of the three accumulators.
    __shared__ float shL[8], sh1[8], sh2[8];
    __shared__ bool  is_last;
    const int lane = threadIdx.x & 31;
    const int w    = threadIdx.x >> 5;
    accL = warp_red(accL);
    a1   = warp_red(a1);
    a2   = warp_red(a2);
    if (lane == 0) { shL[w] = accL; sh1[w] = a1; sh2[w] = a2; }
    __syncthreads();
    if (threadIdx.x == 0) {
        float vL = 0.0f, v1 = 0.0f, v2 = 0.0f;
        #pragma unroll
        for (int k = 0; k < 8; k++) { vL += shL[k]; v1 += sh1[k]; v2 += sh2[k]; }
        g_part_nll[blockIdx.x] = vL;
        g_part_w1[blockIdx.x]  = v1;
        g_part_w2[blockIdx.x]  = v2;
        __threadfence();
        unsigned int old = atomicInc(&g_count, MAIN_BLOCKS - 1);
        is_last = (old == MAIN_BLOCKS - 1);   // counter is now 0 again for next launch
    }
    __syncthreads();

    if (!is_last) return;

    // Last block: deterministic fp64 combine of all partials.
    double sL = 0.0, s1 = 0.0, s2 = 0.0;
    for (int i = threadIdx.x; i < MAIN_BLOCKS; i += MAIN_TPB) {
        sL += (double)__ldcg(&g_part_nll[i]);
        s1 += (double)__ldcg(&g_part_w1[i]);
        s2 += (double)__ldcg(&g_part_w2[i]);
    }
    __shared__ double dL[8], d1[8], d2[8];
    sL = warp_red_d(sL); s1 = warp_red_d(s1); s2 = warp_red_d(s2);
    if (lane == 0) { dL[w] = sL; d1[w] = s1; d2[w] = s2; }
    __syncthreads();
    if (threadIdx.x == 0) {
        double vL = 0.0, v1 = 0.0, v2 = 0.0;
        #pragma unroll
        for (int k = 0; k < 8; k++) { vL += dL[k]; v1 += d1[k]; v2 += d2[k]; }
        double nll = -vL * invN;
        double reg = 0.002 * (sqrt(v1) + sqrt(v2));
        out[0] = (float)(nll + reg);
    }
}

extern "C" void kernel_launch(void* const* d_in, const int* in_sizes, int n_in,
                              void* d_out, int out_size) {
    const float4* p4 = (const float4*)d_in[0];   // output_1: N float32
    const uint4*  l4 = (const uint4*)d_in[1];    // label: N int32
    const float4* w1 = (const float4*)d_in[2];   // W1: 1024x4096 f32
    const float4* w2 = (const float4*)d_in[3];   // W2: 4096x1024 f32
    const int nq  = in_sizes[0] / 4;
    const int nw1 = in_sizes[2] / 4;
    const int nw2 = in_sizes[3] / 4;
    const double invN = 1.0 / (double)in_sizes[0];

    fused_kernel<<<MAIN_BLOCKS, MAIN_TPB>>>(p4, l4, w1, w2, (float*)d_out,
                                            nq, nw1, nw2, invN);
}

// round 7
// speedup vs baseline: 1.1759x; 1.1759x over previous
#include <cuda_runtime.h>
#include <math.h>

#define GRID  888            /* 148 SMs x 6 CTAs: one exact wave at occ 6 */
#define TPB   256
#define STRIDE (GRID * TPB)  /* 227328 */

__device__ float g_part_nll[GRID];
__device__ float g_part_w1[GRID];
__device__ float g_part_w2[GRID];
__device__ unsigned int g_count = 0;   // atomicInc wraps to 0 each launch

// log2(picked): picked = label ? p : 1-p, clamped at 1e-8.
// x = p + g, g = l ? +0.0f : -1.0f via carry-wrapping IMAD; picked = |x|.
static __device__ __forceinline__ float pick_lg2(float p, unsigned int l) {
    float g = __uint_as_float(l * 0x40800000u + 0xBF800000u);
    float x = p + g;
    float pick = fmaxf(fabsf(x), 1e-8f);
    return __log2f(pick);
}

static __device__ __forceinline__ float e4(float4 p, uint4 l) {
    return (pick_lg2(p.x, l.x) + pick_lg2(p.y, l.y))
         + (pick_lg2(p.z, l.z) + pick_lg2(p.w, l.w));
}

static __device__ __forceinline__ float warp_red(float v) {
    #pragma unroll
    for (int o = 16; o; o >>= 1) v += __shfl_down_sync(0xFFFFFFFFu, v, o);
    return v;
}
static __device__ __forceinline__ double warp_red_d(double v) {
    #pragma unroll
    for (int o = 16; o; o >>= 1) v += __shfl_down_sync(0xFFFFFFFFu, v, o);
    return v;
}

extern "C" __global__ void __launch_bounds__(TPB, 6)
fused_kernel(const float4* __restrict__ p4,
             const uint4*  __restrict__ l4,
             const float4* __restrict__ w1,
             const float4* __restrict__ w2,
             float* __restrict__ out,
             int nq, int nw1, int nw2, double invN) {
    const int t0 = blockIdx.x * TPB + threadIdx.x;

    // NLL: unroll x2 across grid-stride -> 4 independent LDG.128 per round.
    float acc0 = 0.0f, acc1 = 0.0f;
    int i = t0;
    for (; i + STRIDE < nq; i += 2 * STRIDE) {
        float4 pa = __ldcs(p4 + i);
        uint4  la = __ldcs(l4 + i);
        float4 pb = __ldcs(p4 + i + STRIDE);
        uint4  lb = __ldcs(l4 + i + STRIDE);
        acc0 += e4(pa, la);
        acc1 += e4(pb, lb);
    }
    if (i < nq) {
        float4 pa = __ldcs(p4 + i);
        uint4  la = __ldcs(l4 + i);
        acc0 += e4(pa, la);
    }
    float accL = acc0 + acc1;   // sum of log2(picked)

    // W1 sum of squares, unroll x2.
    float a1a = 0.0f, a1b = 0.0f;
    i = t0;
    for (; i + STRIDE < nw1; i += 2 * STRIDE) {
        float4 va = __ldcs(w1 + i);
        float4 vb = __ldcs(w1 + i + STRIDE);
        a1a = fmaf(va.x, va.x, a1a); a1a = fmaf(va.y, va.y, a1a);
        a1a = fmaf(va.z, va.z, a1a); a1a = fmaf(va.w, va.w, a1a);
        a1b = fmaf(vb.x, vb.x, a1b); a1b = fmaf(vb.y, vb.y, a1b);
        a1b = fmaf(vb.z, vb.z, a1b); a1b = fmaf(vb.w, vb.w, a1b);
    }
    if (i < nw1) {
        float4 va = __ldcs(w1 + i);
        a1a = fmaf(va.x, va.x, a1a); a1a = fmaf(va.y, va.y, a1a);
        a1a = fmaf(va.z, va.z, a1a); a1a = fmaf(va.w, va.w, a1a);
    }
    float a1 = a1a + a1b;

    // W2 sum of squares, unroll x2.
    float a2a = 0.0f, a2b = 0.0f;
    i = t0;
    for (; i + STRIDE < nw2; i += 2 * STRIDE) {
        float4 va = __ldcs(w2 + i);
        float4 vb = __ldcs(w2 + i + STRIDE);
        a2a = fmaf(va.x, va.x, a2a); a2a = fmaf(va.y, va.y, a2a);
        a2a = fmaf(va.z, va.z, a2a); a2a = fmaf(va.w, va.w, a2a);
        a2b = fmaf(vb.x, vb.x, a2b); a2b = fmaf(vb.y, vb.y, a2b);
        a2b = fmaf(vb.z, vb.z, a2b); a2b = fmaf(vb.w, vb.w, a2b);
    }
    if (i < nw2) {
        float4 va = __ldcs(w2 + i);
        a2a = fmaf(va.x, va.x, a2a); a2a = fmaf(va.y, va.y, a2a);
        a2a = fmaf(va.z, va.z, a2a); a2a = fmaf(va.w, va.w, a2a);
    }
    float a2 = a2a + a2b;

    // Block reduction.
    __shared__ float shL[8], sh1[8], sh2[8];
    __shared__ bool  is_last;
    const int lane = threadIdx.x & 31;
    const int w    = threadIdx.x >> 5;
    accL = warp_red(accL);
    a1   = warp_red(a1);
    a2   = warp_red(a2);
    if (lane == 0) { shL[w] = accL; sh1[w] = a1; sh2[w] = a2; }
    __syncthreads();
    if (threadIdx.x == 0) {
        float vL = 0.0f, v1 = 0.0f, v2 = 0.0f;
        #pragma unroll
        for (int k = 0; k < 8; k++) { vL += shL[k]; v1 += sh1[k]; v2 += sh2[k]; }
        g_part_nll[blockIdx.x] = vL;
        g_part_w1[blockIdx.x]  = v1;
        g_part_w2[blockIdx.x]  = v2;
        __threadfence();
        unsigned int old = atomicInc(&g_count, GRID - 1);
        is_last = (old == GRID - 1);
    }
    __syncthreads();

    if (!is_last) return;

    // Last block: deterministic fp64 combine; fold ln2 and 1/N here.
    double sL = 0.0, s1 = 0.0, s2 = 0.0;
    for (int k = threadIdx.x; k < GRID; k += TPB) {
        sL += (double)__ldcg(&g_part_nll[k]);
        s1 += (double)__ldcg(&g_part_w1[k]);
        s2 += (double)__ldcg(&g_part_w2[k]);
    }
    __shared__ double dL[8], d1[8], d2[8];
    sL = warp_red_d(sL); s1 = warp_red_d(s1); s2 = warp_red_d(s2);
    if (lane == 0) { dL[w] = sL; d1[w] = s1; d2[w] = s2; }
    __syncthreads();
    if (threadIdx.x == 0) {
        double vL = 0.0, v1 = 0.0, v2 = 0.0;
        #pragma unroll
        for (int k = 0; k < 8; k++) { vL += dL[k]; v1 += d1[k]; v2 += d2[k]; }
        double nll = -vL * 0.6931471805599453 * invN;   // log2 -> ln
        double reg = 0.002 * (sqrt(v1) + sqrt(v2));
        out[0] = (float)(nll + reg);
    }
}

extern "C" void kernel_launch(void* const* d_in, const int* in_sizes, int n_in,
                              void* d_out, int out_size) {
    const float4* p4 = (const float4*)d_in[0];   // output_1: N float32
    const uint4*  l4 = (const uint4*)d_in[1];    // label: N int32
    const float4* w1 = (const float4*)d_in[2];   // W1 f32
    const float4* w2 = (const float4*)d_in[3];   // W2 f32
    const int nq  = in_sizes[0] / 4;
    const int nw1 = in_sizes[2] / 4;
    const int nw2 = in_sizes[3] / 4;
    const double invN = 1.0 / (double)in_sizes[0];

    fused_kernel<<<GRID, TPB>>>(p4, l4, w1, w2, (float*)d_out,
                                nq, nw1, nw2, invN);
}